// round 5
// baseline (speedup 1.0000x reference)
#include <cuda_runtime.h>
#include <cuda_bf16.h>

#define BB    64
#define LL    4096
#define DD    256
#define VOCAB 33

// ---- K1 (histogram) ----
#define HCH   16                 // chunks per row
#define HNT   256
#define HNW   (HNT / 32)

// ---- K2/K3 (GEMM) ----
#define RT    4                  // rows per block tile
#define CT    32                 // cols per block tile
#define GNT   256                // 8 warps
#define NRT   (BB / RT)          // 16
#define NCT   (DD / CT)          // 8
#define PPAD  264                // padded row stride (8 mod 32 -> conflict-free 4-row broadcast)

__device__ int   gcnt[BB][VOCAB];   // statically zero; K3 re-zeroes each run
__device__ float g_h[BB][DD];       // layer-1 activations

// ===================== K1: partial histograms =====================
__global__ __launch_bounds__(HNT)
void hist_kernel(const int* __restrict__ X, const int* __restrict__ vlen)
{
    __shared__ int wh[HNW][VOCAB];

    const int row   = blockIdx.x >> 4;     // 0..63
    const int chunk = blockIdx.x & 15;     // 0..15
    const int base  = chunk * HNT;
    const int tid   = threadIdx.x;
    const int warp  = tid >> 5;

    const int vl = vlen[row];
    if (base >= vl) return;

    for (int i = tid; i < HNW * VOCAB; i += HNT)
        (&wh[0][0])[i] = 0;
    __syncthreads();

    const int l = base + tid;
    if (l < vl)
        atomicAdd(&wh[warp][X[row * LL + l]], 1);
    __syncthreads();

    if (tid < VOCAB) {
        int s = 0;
        #pragma unroll
        for (int w = 0; w < HNW; w++) s += wh[w][tid];
        if (s) atomicAdd(&gcnt[row][tid], s);
    }
}

// ===================== K2: layer 1 (pool-on-the-fly + GEMM) =====================
__global__ __launch_bounds__(GNT)
void layer1_kernel(const float* __restrict__ emb,
                   const float* __restrict__ W1,
                   const float* __restrict__ b1)
{
    __shared__ float cnt_s[RT][VOCAB];
    __shared__ alignas(16) float pool_s[RT][PPAD];
    __shared__ alignas(16) float part_s[8][32][4];   // [warp][lane][float4]

    const int r0   = (int)blockIdx.y * RT;
    const int c0   = (int)blockIdx.x * CT;
    const int tid  = threadIdx.x;
    const int warp = tid >> 5;
    const int lane = tid & 31;

    // ---- counts for this row tile ----
    if (tid < RT * VOCAB) {
        const int r = tid / VOCAB, v = tid % VOCAB;
        cnt_s[r][v] = (float)gcnt[r0 + r][v];
    }
    __syncthreads();

    // ---- pooled rows on the fly: thread t owns dim d = t ----
    {
        float e[VOCAB];
        #pragma unroll
        for (int v = 0; v < VOCAB; v++) e[v] = emb[v * DD + tid];  // coalesced, L2-hot
        #pragma unroll
        for (int r = 0; r < RT; r++) {
            float a = 0.0f;
            #pragma unroll
            for (int v = 0; v < VOCAB; v++) a = fmaf(cnt_s[r][v], e[v], a);
            pool_s[r][tid] = a;
        }
    }
    __syncthreads();

    // ---- split-K GEMM: warp owns k in [32*warp, 32*warp+32)
    //      lane: r = lane>>3 (4 rows), 4 cols at c0 + 4*(lane&7)
    const int r    = lane >> 3;
    const int cg   = lane & 7;
    const int cidx = (c0 >> 2) + cg;                 // float4 column index
    const float4* Wv = (const float4*)W1;
    const int kbase = warp * 32;

    float4 acc = make_float4(0.f, 0.f, 0.f, 0.f);
    #pragma unroll 8
    for (int kk = 0; kk < 32; kk++) {
        const int   k = kbase + kk;
        const float s = pool_s[r][k];                // 4-group broadcast, conflict-free
        const float4 w = Wv[k * (DD / 4) + cidx];    // L2-resident LDG.128
        acc.x = fmaf(s, w.x, acc.x);
        acc.y = fmaf(s, w.y, acc.y);
        acc.z = fmaf(s, w.z, acc.z);
        acc.w = fmaf(s, w.w, acc.w);
    }
    *((float4*)part_s[warp][lane]) = acc;
    __syncthreads();

    // ---- reduce 8 warp partials, bias+relu, store h ----
    if (tid < 32) {
        float4 s = make_float4(0.f, 0.f, 0.f, 0.f);
        #pragma unroll
        for (int w = 0; w < 8; w++) {
            const float4 p = *((const float4*)part_s[w][tid]);
            s.x += p.x; s.y += p.y; s.z += p.z; s.w += p.w;
        }
        const int rr = tid >> 3;
        const int cc = c0 + (tid & 7) * 4;
        s.x = fmaxf(s.x + b1[cc + 0], 0.f);
        s.y = fmaxf(s.y + b1[cc + 1], 0.f);
        s.z = fmaxf(s.z + b1[cc + 2], 0.f);
        s.w = fmaxf(s.w + b1[cc + 3], 0.f);
        *((float4*)&g_h[r0 + rr][cc]) = s;
    }
}

// ===================== K3: layer 2 (GEMM) + gcnt cleanup =====================
__global__ __launch_bounds__(GNT)
void layer2_kernel(const float* __restrict__ W2,
                   const float* __restrict__ b2,
                   float* __restrict__ out)
{
    __shared__ alignas(16) float hin_s[RT][PPAD];
    __shared__ alignas(16) float part_s[8][32][4];

    const int r0   = (int)blockIdx.y * RT;
    const int c0   = (int)blockIdx.x * CT;
    const int tid  = threadIdx.x;
    const int warp = tid >> 5;
    const int lane = tid & 31;

    // one block re-zeroes gcnt for the next graph replay
    if (blockIdx.x == 0 && blockIdx.y == 0) {
        for (int i = tid; i < BB * VOCAB; i += GNT)
            (&gcnt[0][0])[i] = 0;
    }

    // ---- load h tile ----
    #pragma unroll
    for (int r = 0; r < RT; r++)
        hin_s[r][tid] = g_h[r0 + r][tid];
    __syncthreads();

    const int r    = lane >> 3;
    const int cg   = lane & 7;
    const int cidx = (c0 >> 2) + cg;
    const float4* Wv = (const float4*)W2;
    const int kbase = warp * 32;

    float4 acc = make_float4(0.f, 0.f, 0.f, 0.f);
    #pragma unroll 8
    for (int kk = 0; kk < 32; kk++) {
        const int   k = kbase + kk;
        const float s = hin_s[r][k];
        const float4 w = Wv[k * (DD / 4) + cidx];
        acc.x = fmaf(s, w.x, acc.x);
        acc.y = fmaf(s, w.y, acc.y);
        acc.z = fmaf(s, w.z, acc.z);
        acc.w = fmaf(s, w.w, acc.w);
    }
    *((float4*)part_s[warp][lane]) = acc;
    __syncthreads();

    if (tid < 32) {
        float4 s = make_float4(0.f, 0.f, 0.f, 0.f);
        #pragma unroll
        for (int w = 0; w < 8; w++) {
            const float4 p = *((const float4*)part_s[w][tid]);
            s.x += p.x; s.y += p.y; s.z += p.z; s.w += p.w;
        }
        const int rr = tid >> 3;
        const int cc = c0 + (tid & 7) * 4;
        s.x = fmaxf(s.x + b2[cc + 0], 0.f);
        s.y = fmaxf(s.y + b2[cc + 1], 0.f);
        s.z = fmaxf(s.z + b2[cc + 2], 0.f);
        s.w = fmaxf(s.w + b2[cc + 3], 0.f);
        *((float4*)&out[(r0 + rr) * DD + cc]) = s;
    }
}

extern "C" void kernel_launch(void* const* d_in, const int* in_sizes, int n_in,
                              void* d_out, int out_size)
{
    const int*   X    = (const int*)d_in[0];
    const int*   vlen = (const int*)d_in[1];
    const float* emb  = (const float*)d_in[2];
    const float* W1   = (const float*)d_in[3];
    const float* b1   = (const float*)d_in[4];
    const float* W2   = (const float*)d_in[5];
    const float* b2   = (const float*)d_in[6];
    float*       out  = (float*)d_out;

    hist_kernel<<<BB * HCH, HNT>>>(X, vlen);
    layer1_kernel<<<dim3(NCT, NRT), GNT>>>(emb, W1, b1);
    layer2_kernel<<<dim3(NCT, NRT), GNT>>>(W2, b2, out);
}

// round 7
// speedup vs baseline: 1.3028x; 1.3028x over previous
#include <cuda_runtime.h>
#include <cuda_bf16.h>

#define BB    64
#define LL    4096
#define DD    256
#define VOCAB 33

// ---- K1 ----
#define NT1         512
#define NWARP1      16
#define HIST_BLOCKS 128          // 64 rows x 2 halves (2048 tokens each)
#define M1_BLOCKS   66           // 33 v x 2 col-halves
#define GRID1       (HIST_BLOCKS + M1_BLOCKS)

// ---- K2 ----
#define NT2         256

__device__ int   gpart[HIST_BLOCKS][VOCAB];  // per-block histogram partials (overwritten)
__device__ float g_M1[VOCAB * DD];           // emb @ W1 (overwritten)

// ============ K1: histograms (blocks 0-127) + M1 = emb@W1 (blocks 128-193) ============
__global__ __launch_bounds__(NT1)
void k1_hist_m1(const int* __restrict__ X,
                const int* __restrict__ vlen,
                const float* __restrict__ emb,
                const float* __restrict__ W1)
{
    __shared__ int   wh[NWARP1][VOCAB];
    __shared__ float embs[DD];
    __shared__ alignas(16) float m1part[4][128];

    const int bid  = blockIdx.x;
    const int tid  = threadIdx.x;
    const int warp = tid >> 5;

    if (bid < HIST_BLOCKS) {
        const int row  = bid >> 1;
        const int half = bid & 1;
        const int vl   = vlen[row];
        const int l0   = half * 2048 + tid * 4;

        if (half * 2048 >= vl) {
            if (tid < VOCAB) gpart[bid][tid] = 0;
            return;
        }
        for (int i = tid; i < NWARP1 * VOCAB; i += NT1)
            (&wh[0][0])[i] = 0;
        __syncthreads();

        if (l0 < vl) {
            int4 xv = ((const int4*)X)[row * (LL / 4) + half * 512 + tid];
            atomicAdd(&wh[warp][xv.x], 1);
            if (l0 + 1 < vl) atomicAdd(&wh[warp][xv.y], 1);
            if (l0 + 2 < vl) atomicAdd(&wh[warp][xv.z], 1);
            if (l0 + 3 < vl) atomicAdd(&wh[warp][xv.w], 1);
        }
        __syncthreads();

        if (tid < VOCAB) {
            int s = 0;
            #pragma unroll
            for (int w = 0; w < NWARP1; w++) s += wh[w][tid];
            gpart[bid][tid] = s;                       // plain store
        }
    } else {
        // M1[v][128*ch .. 128*ch+128) = emb[v] @ W1[:, cols]
        const int j  = bid - HIST_BLOCKS;              // 0..65
        const int v  = j >> 1;
        const int ch = j & 1;

        if (tid < DD) embs[tid] = emb[v * DD + tid];
        __syncthreads();

        const int c   = tid & 127;
        const int g   = tid >> 7;                      // k-quarter
        const int col = ch * 128 + c;

        float acc = 0.0f;
        #pragma unroll 8
        for (int kk = 0; kk < 64; kk++) {
            const int k = g * 64 + kk;
            acc = fmaf(embs[k], W1[k * DD + col], acc);
        }
        m1part[g][c] = acc;
        __syncthreads();

        if (tid < 128)
            g_M1[v * DD + ch * 128 + tid] =
                m1part[0][tid] + m1part[1][tid] + m1part[2][tid] + m1part[3][tid];
    }
}

// ============ K2: h = relu(cnt@M1 + b1); out-half = relu(h@W2 + b2) ============
__global__ __launch_bounds__(NT2)
void k2_mlp(const float* __restrict__ b1,
            const float* __restrict__ W2,
            const float* __restrict__ b2,
            float* __restrict__ out)
{
    __shared__ float cnt_s[VOCAB];
    __shared__ alignas(16) float h_s[DD];
    __shared__ alignas(16) float part2[8][32][4];

    const int r    = (int)blockIdx.x >> 1;             // batch row
    const int half = (int)blockIdx.x & 1;              // col half
    const int tid  = threadIdx.x;

    if (tid < VOCAB)
        cnt_s[tid] = (float)(gpart[2 * r][tid] + gpart[2 * r + 1][tid]);
    __syncthreads();

    // ---- layer 1 via precomputed M1: 33 FMAs per output dim ----
    {
        float a = b1[tid];
        #pragma unroll
        for (int v = 0; v < VOCAB; v++)
            a = fmaf(cnt_s[v], g_M1[v * DD + tid], a); // coalesced, L2-hot
        h_s[tid] = fmaxf(a, 0.0f);
    }
    __syncthreads();

    // ---- layer 2 over cols [128*half, +128), split-K x8 ----
    {
        const int lane = tid & 31;                     // float4 col in half
        const int g    = tid >> 5;                     // k-group 0..7
        const int cf4  = half * 32 + lane;
        const float4* W2v = (const float4*)W2;

        float4 acc = make_float4(0.f, 0.f, 0.f, 0.f);
        #pragma unroll 8
        for (int kk = 0; kk < 32; kk++) {
            const int   k = g * 32 + kk;
            const float s = h_s[k];
            const float4 w = W2v[k * (DD / 4) + cf4];
            acc.x = fmaf(s, w.x, acc.x);
            acc.y = fmaf(s, w.y, acc.y);
            acc.z = fmaf(s, w.z, acc.z);
            acc.w = fmaf(s, w.w, acc.w);
        }
        *((float4*)&part2[g][lane][0]) = acc;
        __syncthreads();

        if (tid < 32) {
            float4 s = make_float4(0.f, 0.f, 0.f, 0.f);
            #pragma unroll
            for (int g2 = 0; g2 < 8; g2++) {
                const float4 p = *((const float4*)&part2[g2][tid][0]);
                s.x += p.x; s.y += p.y; s.z += p.z; s.w += p.w;
            }
            const float4 bb = ((const float4*)b2)[half * 32 + tid];
            s.x = fmaxf(s.x + bb.x, 0.f);
            s.y = fmaxf(s.y + bb.y, 0.f);
            s.z = fmaxf(s.z + bb.z, 0.f);
            s.w = fmaxf(s.w + bb.w, 0.f);
            *((float4*)&out[r * DD + half * 128 + 4 * tid]) = s;
        }
    }
}

extern "C" void kernel_launch(void* const* d_in, const int* in_sizes, int n_in,
                              void* d_out, int out_size)
{
    const int*   X    = (const int*)d_in[0];
    const int*   vlen = (const int*)d_in[1];
    const float* emb  = (const float*)d_in[2];
    const float* W1   = (const float*)d_in[3];
    const float* b1   = (const float*)d_in[4];
    const float* W2   = (const float*)d_in[5];
    const float* b2   = (const float*)d_in[6];
    float*       out  = (float*)d_out;

    k1_hist_m1<<<GRID1, NT1>>>(X, vlen, emb, W1);
    k2_mlp<<<BB * 2, NT2>>>(b1, W2, b2, out);
}

// round 8
// speedup vs baseline: 1.3299x; 1.0208x over previous
#include <cuda_runtime.h>
#include <cuda_bf16.h>

#define BB    64
#define LL    4096
#define DD    256
#define VOCAB 33

// ---- K1 ----
#define NT1         512
#define NWARP1      16
#define HIST_BLOCKS 128          // 64 rows x 2 halves (2048 tokens each)
#define M1_BLOCKS   66           // 33 v x 2 col-halves
#define GRID1       (HIST_BLOCKS + M1_BLOCKS)

// ---- K2 ----
#define NT2   256
#define CT2   32                 // cols per block tile
#define NCT2  (DD / CT2)         // 8 col tiles
#define GRID2 (BB * NCT2)        // 512 blocks

__device__ int   gpart[HIST_BLOCKS][VOCAB];  // per-block histogram partials (overwritten)
__device__ float g_M1[VOCAB * DD];           // emb @ W1 (overwritten)

// ============ K1: histograms (blocks 0-127) + M1 = emb@W1 (blocks 128-193) ============
__global__ __launch_bounds__(NT1)
void k1_hist_m1(const int* __restrict__ X,
                const int* __restrict__ vlen,
                const float* __restrict__ emb,
                const float* __restrict__ W1)
{
    __shared__ int   wh[NWARP1][VOCAB];
    __shared__ float embs[DD];
    __shared__ alignas(16) float m1part[4][128];

    const int bid  = blockIdx.x;
    const int tid  = threadIdx.x;
    const int warp = tid >> 5;

    if (bid < HIST_BLOCKS) {
        const int row  = bid >> 1;
        const int half = bid & 1;
        const int vl   = vlen[row];
        const int l0   = half * 2048 + tid * 4;

        if (half * 2048 >= vl) {
            if (tid < VOCAB) gpart[bid][tid] = 0;
            return;
        }
        for (int i = tid; i < NWARP1 * VOCAB; i += NT1)
            (&wh[0][0])[i] = 0;
        __syncthreads();

        if (l0 < vl) {
            int4 xv = ((const int4*)X)[row * (LL / 4) + half * 512 + tid];
            atomicAdd(&wh[warp][xv.x], 1);
            if (l0 + 1 < vl) atomicAdd(&wh[warp][xv.y], 1);
            if (l0 + 2 < vl) atomicAdd(&wh[warp][xv.z], 1);
            if (l0 + 3 < vl) atomicAdd(&wh[warp][xv.w], 1);
        }
        __syncthreads();

        if (tid < VOCAB) {
            int s = 0;
            #pragma unroll
            for (int w = 0; w < NWARP1; w++) s += wh[w][tid];
            gpart[bid][tid] = s;                       // plain store
        }
    } else {
        // M1[v][128*ch .. 128*ch+128) = emb[v] @ W1[:, cols]
        const int j  = bid - HIST_BLOCKS;              // 0..65
        const int v  = j >> 1;
        const int ch = j & 1;

        if (tid < DD) embs[tid] = emb[v * DD + tid];
        __syncthreads();

        const int c   = tid & 127;
        const int g   = tid >> 7;                      // k-quarter
        const int col = ch * 128 + c;

        float acc = 0.0f;
        #pragma unroll 8
        for (int kk = 0; kk < 64; kk++) {
            const int k = g * 64 + kk;
            acc = fmaf(embs[k], W1[k * DD + col], acc);
        }
        m1part[g][c] = acc;
        __syncthreads();

        if (tid < 128)
            g_M1[v * DD + ch * 128 + tid] =
                m1part[0][tid] + m1part[1][tid] + m1part[2][tid] + m1part[3][tid];
    }
}

// ============ K2: per (row, 32-col tile): h = relu(cnt@M1+b1); out = relu(h@W2+b2) ============
__global__ __launch_bounds__(NT2)
void k2_mlp(const float* __restrict__ b1,
            const float* __restrict__ W2,
            const float* __restrict__ b2,
            float* __restrict__ out)
{
    __shared__ float cnt_s[VOCAB + 3];                 // padded
    __shared__ alignas(16) float h_s[DD];
    __shared__ alignas(16) float4 part_s[32][8];       // [k-group][float4-col]

    const int r    = (int)blockIdx.x >> 3;             // batch row
    const int ct   = (int)blockIdx.x & 7;              // col tile
    const int c0   = ct * CT2;
    const int tid  = threadIdx.x;

    // counts (2 L2 loads per v; padded entries zeroed)
    if (tid < VOCAB + 3)
        cnt_s[tid] = (tid < VOCAB)
                   ? (float)(gpart[2 * r][tid] + gpart[2 * r + 1][tid]) : 0.0f;
    __syncthreads();

    // ---- layer 1: h[tid] = relu(b1 + sum_v cnt[v]*M1[v][tid]), 2 accumulators ----
    {
        float a0 = b1[tid], a1 = 0.0f;
        #pragma unroll
        for (int v = 0; v < 36; v += 2) {              // padded to even; cnt[33..35]=0
            a0 = fmaf(cnt_s[v],     g_M1[v * DD + tid],       a0);
            a1 = fmaf(cnt_s[v + 1], g_M1[(v + 1) * DD + tid], a1);
        }
        h_s[tid] = fmaxf(a0 + a1, 0.0f);
    }
    __syncthreads();

    // ---- layer 2: 32-way split-K, 8 independent LDG.128 per thread ----
    {
        const int g    = tid >> 3;                     // k-group 0..31 (k in [8g, 8g+8))
        const int lane = tid & 7;                      // float4 col in tile
        const int cf4  = (c0 >> 2) + lane;
        const float4* W2v = (const float4*)W2;
        const int kbase = g * 8;

        float4 acc = make_float4(0.f, 0.f, 0.f, 0.f);
        #pragma unroll
        for (int kk = 0; kk < 8; kk++) {               // fully unrolled: 8 loads in flight
            const int   k = kbase + kk;
            const float s = h_s[k];
            const float4 w = W2v[k * (DD / 4) + cf4];
            acc.x = fmaf(s, w.x, acc.x);
            acc.y = fmaf(s, w.y, acc.y);
            acc.z = fmaf(s, w.z, acc.z);
            acc.w = fmaf(s, w.w, acc.w);
        }
        part_s[g][lane] = acc;
        __syncthreads();

        // reduce 32 partials per scalar col; 32 threads, one col each
        if (tid < CT2) {
            const int cf = tid >> 2;                   // float4 index
            const int el = tid & 3;
            float s = 0.0f;
            #pragma unroll
            for (int g2 = 0; g2 < 32; g2++) {
                const float4 p = part_s[g2][cf];
                s += (el == 0) ? p.x : (el == 1) ? p.y : (el == 2) ? p.z : p.w;
            }
            out[r * DD + c0 + tid] = fmaxf(s + b2[c0 + tid], 0.0f);
        }
    }
}

extern "C" void kernel_launch(void* const* d_in, const int* in_sizes, int n_in,
                              void* d_out, int out_size)
{
    const int*   X    = (const int*)d_in[0];
    const int*   vlen = (const int*)d_in[1];
    const float* emb  = (const float*)d_in[2];
    const float* W1   = (const float*)d_in[3];
    const float* b1   = (const float*)d_in[4];
    const float* W2   = (const float*)d_in[5];
    const float* b2   = (const float*)d_in[6];
    float*       out  = (float*)d_out;

    k1_hist_m1<<<GRID1, NT1>>>(X, vlen, emb, W1);
    k2_mlp<<<GRID2, NT2>>>(b1, W2, b2, out);
}

// round 9
// speedup vs baseline: 1.5657x; 1.1774x over previous
#include <cuda_runtime.h>
#include <cuda_bf16.h>
#include <cooperative_groups.h>
namespace cg = cooperative_groups;

#define BB    64
#define LL    4096
#define DD    256
#define VOCAB 33

#define NT          512
#define NWARP       16
#define HIST_BLOCKS 128                // 64 rows x 2 halves (2048 tokens)
#define M1_BASE     HIST_BLOCKS
#define M1_BLOCKS   66                 // 33 v x 2 col-halves
#define GRID        256                // phase B: 64 rows x 4 col-quarters

__device__ int    gpart[HIST_BLOCKS][VOCAB];
__device__ float4 g_M1[VOCAB * (DD / 4)];      // emb @ W1, float4-aligned

__global__ __launch_bounds__(NT, 2)
void prot_net_coop(const int* __restrict__ X,
                   const int* __restrict__ vlen,
                   const float* __restrict__ emb,
                   const float* __restrict__ W1,
                   const float* __restrict__ b1,
                   const float* __restrict__ W2,
                   const float* __restrict__ b2,
                   float* __restrict__ out)
{
    __shared__ int   wh[NWARP][VOCAB];
    __shared__ float embs[DD];
    __shared__ alignas(16) float4 m1part[16][32];
    __shared__ float cnt_s[VOCAB];
    __shared__ alignas(16) float hpart[2][DD];
    __shared__ alignas(16) float h_s[DD];
    __shared__ alignas(16) float4 part_s[32][16];
    __shared__ alignas(16) float4 p2[4][16];

    const int bid  = blockIdx.x;
    const int tid  = threadIdx.x;
    const int warp = tid >> 5;

    // ================= PHASE A =================
    if (bid < HIST_BLOCKS) {
        const int row  = bid >> 1;
        const int half = bid & 1;
        // issue X load immediately (always in-bounds), vlen concurrently
        const int4 xv = ((const int4*)X)[row * (LL / 4) + half * 512 + tid];
        const int  vl = vlen[row];
        const int  l0 = half * 2048 + tid * 4;

        for (int i = tid; i < NWARP * VOCAB; i += NT)
            (&wh[0][0])[i] = 0;
        __syncthreads();

        if (l0 < vl) {
            atomicAdd(&wh[warp][xv.x], 1);
            if (l0 + 1 < vl) atomicAdd(&wh[warp][xv.y], 1);
            if (l0 + 2 < vl) atomicAdd(&wh[warp][xv.z], 1);
            if (l0 + 3 < vl) atomicAdd(&wh[warp][xv.w], 1);
        }
        __syncthreads();

        if (tid < VOCAB) {
            int s = 0;
            #pragma unroll
            for (int w = 0; w < NWARP; w++) s += wh[w][tid];
            gpart[bid][tid] = s;
        }
    } else if (bid < M1_BASE + M1_BLOCKS) {
        // M1 tile: v = row of emb, ch = col half of W1
        const int j  = bid - M1_BASE;
        const int v  = j >> 1;
        const int ch = j & 1;

        if (tid < DD) embs[tid] = emb[v * DD + tid];
        __syncthreads();

        const int f4c = tid & 31;              // float4 col in half
        const int g   = tid >> 5;              // k-group 0..15
        const float4* W1v = (const float4*)W1;

        float4 acc = make_float4(0.f, 0.f, 0.f, 0.f);
        #pragma unroll
        for (int kk = 0; kk < 16; kk++) {      // 16 independent LDG.128
            const int   k = g * 16 + kk;
            const float e = embs[k];
            const float4 w = W1v[k * (DD / 4) + ch * 32 + f4c];
            acc.x = fmaf(e, w.x, acc.x);
            acc.y = fmaf(e, w.y, acc.y);
            acc.z = fmaf(e, w.z, acc.z);
            acc.w = fmaf(e, w.w, acc.w);
        }
        m1part[g][f4c] = acc;
        __syncthreads();

        if (tid < 32) {
            float4 s = make_float4(0.f, 0.f, 0.f, 0.f);
            #pragma unroll
            for (int g2 = 0; g2 < 16; g2++) {
                const float4 p = m1part[g2][tid];
                s.x += p.x; s.y += p.y; s.z += p.z; s.w += p.w;
            }
            g_M1[v * (DD / 4) + ch * 32 + tid] = s;
        }
    }
    // blocks 194..255: idle in phase A

    // ================= GRID BARRIER =================
    cg::this_grid().sync();

    // ================= PHASE B: (row, col-quarter) =================
    {
        const int r   = bid >> 2;
        const int qt  = bid & 3;               // 64-col quarter

        // --- prefetch W2 quarter-tile: 8 independent LDG.128 (no deps on h) ---
        const int kg   = tid >> 4;             // k-group 0..31, k in [8kg, 8kg+8)
        const int lane = tid & 15;             // float4 col in quarter
        const float4* W2v = (const float4*)W2;
        float4 w[8];
        #pragma unroll
        for (int j = 0; j < 8; j++)
            w[j] = W2v[(kg * 8 + j) * (DD / 4) + qt * 16 + lane];

        const float b1v = (tid < DD) ? b1[tid] : 0.0f;   // prefetch bias

        if (tid < VOCAB)
            cnt_s[tid] = (float)(gpart[2 * r][tid] + gpart[2 * r + 1][tid]);
        __syncthreads();

        // --- h = relu(cnt @ M1 + b1), 2-way vocab split ---
        {
            const int q = tid >> 8;            // 0/1
            const int d = tid & 255;
            const float* M1f = (const float*)g_M1;
            float a0 = 0.f, a1 = 0.f;
            if (q == 0) {
                #pragma unroll
                for (int v = 0; v < 17; v += 2) {
                    a0 = fmaf(cnt_s[v], M1f[v * DD + d], a0);
                    if (v + 1 < 17) a1 = fmaf(cnt_s[v + 1], M1f[(v + 1) * DD + d], a1);
                }
            } else {
                #pragma unroll
                for (int v = 17; v < 33; v += 2) {
                    a0 = fmaf(cnt_s[v], M1f[v * DD + d], a0);
                    a1 = fmaf(cnt_s[v + 1], M1f[(v + 1) * DD + d], a1);
                }
            }
            hpart[q][d] = a0 + a1;
        }
        __syncthreads();
        if (tid < DD)
            h_s[tid] = fmaxf(hpart[0][tid] + hpart[1][tid] + b1v, 0.0f);
        __syncthreads();

        // --- layer 2: FMA with prefetched W2 regs ---
        {
            float4 acc = make_float4(0.f, 0.f, 0.f, 0.f);
            #pragma unroll
            for (int j = 0; j < 8; j++) {
                const float s = h_s[kg * 8 + j];
                acc.x = fmaf(s, w[j].x, acc.x);
                acc.y = fmaf(s, w[j].y, acc.y);
                acc.z = fmaf(s, w[j].z, acc.z);
                acc.w = fmaf(s, w[j].w, acc.w);
            }
            part_s[kg][lane] = acc;
        }
        __syncthreads();

        // --- two-stage reduce of 32 k-groups ---
        if (tid < 64) {
            const int l16 = tid & 15;
            const int qq  = tid >> 4;
            float4 s = make_float4(0.f, 0.f, 0.f, 0.f);
            #pragma unroll
            for (int g2 = 0; g2 < 8; g2++) {
                const float4 p = part_s[qq * 8 + g2][l16];
                s.x += p.x; s.y += p.y; s.z += p.z; s.w += p.w;
            }
            p2[qq][l16] = s;
        }
        __syncthreads();
        if (tid < 16) {
            float4 s = make_float4(0.f, 0.f, 0.f, 0.f);
            #pragma unroll
            for (int qq = 0; qq < 4; qq++) {
                const float4 p = p2[qq][tid];
                s.x += p.x; s.y += p.y; s.z += p.z; s.w += p.w;
            }
            const float4 bb = ((const float4*)b2)[qt * 16 + tid];
            s.x = fmaxf(s.x + bb.x, 0.f);
            s.y = fmaxf(s.y + bb.y, 0.f);
            s.z = fmaxf(s.z + bb.z, 0.f);
            s.w = fmaxf(s.w + bb.w, 0.f);
            *((float4*)&out[r * DD + qt * 64 + 4 * tid]) = s;
        }
    }
}

extern "C" void kernel_launch(void* const* d_in, const int* in_sizes, int n_in,
                              void* d_out, int out_size)
{
    const int*   X    = (const int*)d_in[0];
    const int*   vlen = (const int*)d_in[1];
    const float* emb  = (const float*)d_in[2];
    const float* W1   = (const float*)d_in[3];
    const float* b1   = (const float*)d_in[4];
    const float* W2   = (const float*)d_in[5];
    const float* b2   = (const float*)d_in[6];
    float*       out  = (float*)d_out;

    void* args[] = { (void*)&X, (void*)&vlen, (void*)&emb, (void*)&W1,
                     (void*)&b1, (void*)&W2, (void*)&b2, (void*)&out };
    cudaLaunchCooperativeKernel((void*)prot_net_coop,
                                dim3(GRID), dim3(NT), args, 0, (cudaStream_t)0);
}

// round 10
// speedup vs baseline: 1.5950x; 1.0187x over previous
#include <cuda_runtime.h>
#include <cuda_bf16.h>
#include <cooperative_groups.h>
namespace cg = cooperative_groups;

#define BB    64
#define LL    4096
#define DD    256
#define VOCAB 33
#define VPAD  40                  // vocab padded to 8 groups of 5

#define NT          512
#define NWARP       16
#define HIST_BLOCKS 64            // one full row per block
#define M1_BASE     HIST_BLOCKS
#define M1_BLOCKS   66            // 33 v x 2 col-halves
#define GRID        130           // <= 148 SMs at occ 1

__device__ int    gcnt[BB][VOCAB];
__device__ float4 g_M1[VPAD * (DD / 4)];   // rows 33..39 never written -> stay 0

__global__ __launch_bounds__(NT, 1)
void prot_net_coop(const int* __restrict__ X,
                   const int* __restrict__ vlen,
                   const float* __restrict__ emb,
                   const float* __restrict__ W1,
                   const float* __restrict__ b1,
                   const float* __restrict__ W2,
                   const float* __restrict__ b2,
                   float* __restrict__ out)
{
    __shared__ int   wh[NWARP][VOCAB];
    __shared__ float embs[DD];
    __shared__ alignas(16) float4 m1part[16][32];
    __shared__ float cnt_s[VPAD];
    __shared__ alignas(16) float4 hp[8][64];     // h partials: [vocab-group][float4-dim]
    __shared__ alignas(16) float  h_s[DD];
    __shared__ alignas(16) float4 p2[16][32];    // layer-2 partials

    const int bid  = blockIdx.x;
    const int tid  = threadIdx.x;
    const int warp = tid >> 5;

    // ================= PHASE A =================
    if (bid < HIST_BLOCKS) {
        const int row = bid;
        // issue both X loads up front (always in-bounds)
        const int4 xa = ((const int4*)X)[row * (LL / 4) + tid];
        const int4 xb = ((const int4*)X)[row * (LL / 4) + 512 + tid];
        const int  vl = vlen[row];
        const int  la = tid * 4;
        const int  lb = 2048 + tid * 4;

        for (int i = tid; i < NWARP * VOCAB; i += NT)
            (&wh[0][0])[i] = 0;
        __syncthreads();

        if (la < vl) {
            atomicAdd(&wh[warp][xa.x], 1);
            if (la + 1 < vl) atomicAdd(&wh[warp][xa.y], 1);
            if (la + 2 < vl) atomicAdd(&wh[warp][xa.z], 1);
            if (la + 3 < vl) atomicAdd(&wh[warp][xa.w], 1);
        }
        if (lb < vl) {
            atomicAdd(&wh[warp][xb.x], 1);
            if (lb + 1 < vl) atomicAdd(&wh[warp][xb.y], 1);
            if (lb + 2 < vl) atomicAdd(&wh[warp][xb.z], 1);
            if (lb + 3 < vl) atomicAdd(&wh[warp][xb.w], 1);
        }
        __syncthreads();

        if (tid < VOCAB) {
            int s = 0;
            #pragma unroll
            for (int w = 0; w < NWARP; w++) s += wh[w][tid];
            gcnt[row][tid] = s;
        }
    } else {
        // M1[v][128*ch .. +128) = emb[v] @ W1[:, cols]
        const int j  = bid - M1_BASE;          // 0..65
        const int v  = j >> 1;
        const int ch = j & 1;

        if (tid < DD) embs[tid] = emb[v * DD + tid];
        __syncthreads();

        const int f4c = tid & 31;
        const int g   = tid >> 5;              // 16 k-groups
        const float4* W1v = (const float4*)W1;

        float4 acc = make_float4(0.f, 0.f, 0.f, 0.f);
        #pragma unroll
        for (int kk = 0; kk < 16; kk++) {      // 16 independent LDG.128
            const int   k = g * 16 + kk;
            const float e = embs[k];
            const float4 w = W1v[k * (DD / 4) + ch * 32 + f4c];
            acc.x = fmaf(e, w.x, acc.x);
            acc.y = fmaf(e, w.y, acc.y);
            acc.z = fmaf(e, w.z, acc.z);
            acc.w = fmaf(e, w.w, acc.w);
        }
        m1part[g][f4c] = acc;
        __syncthreads();

        if (tid < 32) {
            float4 s = make_float4(0.f, 0.f, 0.f, 0.f);
            #pragma unroll
            for (int g2 = 0; g2 < 16; g2++) {
                const float4 p = m1part[g2][tid];
                s.x += p.x; s.y += p.y; s.z += p.z; s.w += p.w;
            }
            g_M1[v * (DD / 4) + ch * 32 + tid] = s;
        }
    }

    // ================= GRID BARRIER =================
    cg::this_grid().sync();

    // ================= PHASE B: (row, 128-col half), blocks 0..127 =================
    if (bid < 128) {
        const int r    = bid >> 1;
        const int half = bid & 1;

        if (tid < VPAD)
            cnt_s[tid] = (tid < VOCAB) ? (float)gcnt[r][tid] : 0.0f;
        __syncthreads();

        // --- h = cnt @ M1 : 8 vocab-groups x 64 float4-dims, <=5 indep. float4 loads ---
        {
            const int d4 = tid & 63;           // float4 dim
            const int q  = tid >> 6;           // vocab group 0..7 (5 each, padded)
            float4 a = make_float4(0.f, 0.f, 0.f, 0.f);
            #pragma unroll
            for (int j = 0; j < 5; j++) {
                const int   v = q * 5 + j;
                const float c = cnt_s[v];
                const float4 m = g_M1[v * (DD / 4) + d4];  // L2-hot, independent
                a.x = fmaf(c, m.x, a.x);
                a.y = fmaf(c, m.y, a.y);
                a.z = fmaf(c, m.z, a.z);
                a.w = fmaf(c, m.w, a.w);
            }
            hp[q][d4] = a;
        }
        __syncthreads();

        if (tid < DD) {
            const int f4 = tid >> 2, el = tid & 3;
            float s = b1[tid];
            #pragma unroll
            for (int q = 0; q < 8; q++) {
                const float4 p = hp[q][f4];
                s += (el == 0) ? p.x : (el == 1) ? p.y : (el == 2) ? p.z : p.w;
            }
            h_s[tid] = fmaxf(s, 0.0f);
        }
        __syncthreads();

        // --- layer 2 over cols [128*half, +128): 16-way split-K, 16 indep. LDG.128 ---
        {
            const int kg   = tid >> 5;         // k-group 0..15 (16 k each)
            const int lane = tid & 31;         // float4 col in half
            const int cf4  = half * 32 + lane;
            const float4* W2v = (const float4*)W2;

            float4 acc0 = make_float4(0.f, 0.f, 0.f, 0.f);
            float4 acc1 = make_float4(0.f, 0.f, 0.f, 0.f);
            #pragma unroll
            for (int kk = 0; kk < 16; kk += 2) {   // 16 independent loads, 2 acc chains
                const int k0 = kg * 16 + kk;
                const float s0 = h_s[k0];
                const float s1 = h_s[k0 + 1];
                const float4 w0 = W2v[k0 * (DD / 4) + cf4];
                const float4 w1 = W2v[(k0 + 1) * (DD / 4) + cf4];
                acc0.x = fmaf(s0, w0.x, acc0.x);
                acc0.y = fmaf(s0, w0.y, acc0.y);
                acc0.z = fmaf(s0, w0.z, acc0.z);
                acc0.w = fmaf(s0, w0.w, acc0.w);
                acc1.x = fmaf(s1, w1.x, acc1.x);
                acc1.y = fmaf(s1, w1.y, acc1.y);
                acc1.z = fmaf(s1, w1.z, acc1.z);
                acc1.w = fmaf(s1, w1.w, acc1.w);
            }
            acc0.x += acc1.x; acc0.y += acc1.y; acc0.z += acc1.z; acc0.w += acc1.w;
            p2[kg][lane] = acc0;
        }
        __syncthreads();

        if (tid < 32) {
            float4 s = make_float4(0.f, 0.f, 0.f, 0.f);
            #pragma unroll
            for (int g2 = 0; g2 < 16; g2++) {
                const float4 p = p2[g2][tid];
                s.x += p.x; s.y += p.y; s.z += p.z; s.w += p.w;
            }
            const float4 bb = ((const float4*)b2)[half * 32 + tid];
            s.x = fmaxf(s.x + bb.x, 0.f);
            s.y = fmaxf(s.y + bb.y, 0.f);
            s.z = fmaxf(s.z + bb.z, 0.f);
            s.w = fmaxf(s.w + bb.w, 0.f);
            *((float4*)&out[r * DD + half * 128 + 4 * tid]) = s;
        }
    }
}

extern "C" void kernel_launch(void* const* d_in, const int* in_sizes, int n_in,
                              void* d_out, int out_size)
{
    const int*   X    = (const int*)d_in[0];
    const int*   vlen = (const int*)d_in[1];
    const float* emb  = (const float*)d_in[2];
    const float* W1   = (const float*)d_in[3];
    const float* b1   = (const float*)d_in[4];
    const float* W2   = (const float*)d_in[5];
    const float* b2   = (const float*)d_in[6];
    float*       out  = (float*)d_out;

    void* args[] = { (void*)&X, (void*)&vlen, (void*)&emb, (void*)&W1,
                     (void*)&b1, (void*)&W2, (void*)&b2, (void*)&out };
    cudaLaunchCooperativeKernel((void*)prot_net_coop,
                                dim3(GRID), dim3(NT), args, 0, (cudaStream_t)0);
}